// round 2
// baseline (speedup 1.0000x reference)
#include <cuda_runtime.h>
#include <math.h>

// Problem dims (fixed by reference)
#define TT 32
#define NB 16
#define DD 256
#define AA 256
#define F1 512
#define F2 256

// Scratch (allocation-free: __device__ globals)
__device__ float g_s2[TT * NB * DD];        // stage-1 output spikes  [T*N, D]
__device__ float g_buf1[TT * NB * F1];      // pre1 / h1 (in-place)   [T*N, F1]
__device__ float g_buf2[TT * NB * F2];      // pre2 (raw GEMM2 out)   [T*N, F2]

// ---------------------------------------------------------------------------
// Stage 1: one warp per (n,d) chain. Each thread owns 8 'a' lanes.
// Per t: h = x0*W0[a] + x1*W1[a] + b_sdc[a]
//        i = 0.5*i + h                      (exp_filter, decay 0.5)
//        v1 += (i - v1)*0.5 ; s1 = v1>=1 ; v1 *= (1-s1)   (LIF tau=2)
//        syn = syn*sd + s1                  (SynapseFilter decay 1-sigmoid(w_syn))
//        z = sum_a syn*W_pool[a] + b_pool   (warp xor-reduce)
//        v2 += (z - v2)*0.5 ; s2 = v2>=1 ; v2 *= (1-s2)
// ---------------------------------------------------------------------------
__global__ void stage1_kernel(const float* __restrict__ x,
                              const float* __restrict__ W_sdc,
                              const float* __restrict__ b_sdc,
                              const float* __restrict__ w_syn,
                              const float* __restrict__ W_pool,
                              const float* __restrict__ b_pool) {
    int gwarp = (blockIdx.x * blockDim.x + threadIdx.x) >> 5;
    int lane  = threadIdx.x & 31;
    if (gwarp >= NB * DD) return;
    int n = gwarp >> 8;          // / DD
    int d = gwarp & (DD - 1);

    float sd = 1.0f - 1.0f / (1.0f + expf(-w_syn[0]));
    float bp = b_pool[0];

    float w0[8], w1[8], bs[8], wp[8];
#pragma unroll
    for (int j = 0; j < 8; j++) {
        int a = j * 32 + lane;           // coalesced per j
        w0[j] = W_sdc[a];
        w1[j] = W_sdc[AA + a];
        bs[j] = b_sdc[a];
        wp[j] = W_pool[a];
    }

    float is[8], v1[8], sy[8];
#pragma unroll
    for (int j = 0; j < 8; j++) { is[j] = 0.f; v1[j] = 0.f; sy[j] = 0.f; }
    float v2 = 0.f;

    const float* xp = x + (n * 2) * DD + d;   // x[t][n][i][d]
#pragma unroll 1
    for (int t = 0; t < TT; t++) {
        float x0 = xp[(size_t)t * (NB * 2 * DD)];
        float x1 = xp[(size_t)t * (NB * 2 * DD) + DD];
        float z = 0.f;
#pragma unroll
        for (int j = 0; j < 8; j++) {
            float h = x0 * w0[j] + x1 * w1[j] + bs[j];
            is[j] = is[j] * 0.5f + h;
            v1[j] = v1[j] + (is[j] - v1[j]) * 0.5f;
            float s = (v1[j] >= 1.0f) ? 1.0f : 0.0f;
            v1[j] *= (1.0f - s);
            sy[j] = sy[j] * sd + s;
            z += sy[j] * wp[j];
        }
        // full-warp xor reduce
#pragma unroll
        for (int o = 16; o; o >>= 1) z += __shfl_xor_sync(0xffffffffu, z, o);
        z += bp;
        v2 = v2 + (z - v2) * 0.5f;
        float s2 = (v2 >= 1.0f) ? 1.0f : 0.0f;
        v2 *= (1.0f - s2);
        if (lane == 0) g_s2[(t * NB + n) * DD + d] = s2;
    }
}

// ---------------------------------------------------------------------------
// Small GEMM: C[M,Nc] = A[M,K] @ B[K,Nc] + bias[Nc]
// TPB threads (one output col each), ROWS rows per block.
// A tile staged in smem [k][r] for conflict-free vector reads.
// grid = (Nc/TPB, M/ROWS)
// ---------------------------------------------------------------------------
template <int K, int ROWS, int TPB>
__global__ void gemm_bias_kernel(const float* __restrict__ Amat,
                                 const float* __restrict__ Bmat,
                                 const float* __restrict__ bias,
                                 float* __restrict__ C, int Nc) {
    __shared__ float As[ROWS * K];
    int col  = blockIdx.x * TPB + threadIdx.x;
    int row0 = blockIdx.y * ROWS;

#pragma unroll 4
    for (int idx = threadIdx.x; idx < ROWS * K; idx += TPB) {
        int r = idx / K;
        int k = idx - r * K;                 // consecutive tid -> consecutive k (coalesced)
        As[k * ROWS + r] = Amat[(size_t)(row0 + r) * K + k];
    }
    __syncthreads();

    float acc[ROWS];
#pragma unroll
    for (int r = 0; r < ROWS; r++) acc[r] = 0.f;

    const float* bpcol = Bmat + col;
#pragma unroll 8
    for (int k = 0; k < K; k++) {
        float b = bpcol[(size_t)k * Nc];
#pragma unroll
        for (int r = 0; r < ROWS; r++)
            acc[r] = fmaf(As[k * ROWS + r], b, acc[r]);
    }
    float bb = bias[col];
#pragma unroll
    for (int r = 0; r < ROWS; r++)
        C[(size_t)(row0 + r) * Nc + col] = acc[r] + bb;
}

// ---------------------------------------------------------------------------
// In-place LIF scan over leading T dim: buf[t*C + c], C independent chains.
// ---------------------------------------------------------------------------
__global__ void lif_scan_kernel(float* __restrict__ buf, int C) {
    int c = blockIdx.x * blockDim.x + threadIdx.x;
    if (c >= C) return;
    float v = 0.f;
#pragma unroll 1
    for (int t = 0; t < TT; t++) {
        float xv = buf[(size_t)t * C + c];
        v = v + (xv - v) * 0.5f;
        float s = (v >= 1.0f) ? 1.0f : 0.0f;
        v *= (1.0f - s);
        buf[(size_t)t * C + c] = s;
    }
}

// ---------------------------------------------------------------------------
// Fused head: LIF-scan pre2 (per-thread chain), dot with W_out, cumsum over t.
// One block (256 threads = F2 lanes) per n. Per-warp shfl reduce into smem
// partials [t][warp]; single barrier; warp 0 does final sums + inclusive scan
// across the 32 timesteps (TT == warpsize).
// ---------------------------------------------------------------------------
__global__ void head_kernel(const float* __restrict__ W_out,
                            const float* __restrict__ b_out,
                            float* __restrict__ out) {
    int n    = blockIdx.x;
    int tid  = threadIdx.x;
    int lane = tid & 31;
    __shared__ float red[TT * 8];
    float w  = W_out[tid];
    float v  = 0.f;
#pragma unroll 1
    for (int t = 0; t < TT; t++) {
        float xv = g_buf2[(size_t)(t * NB + n) * F2 + tid];
        v = v + (xv - v) * 0.5f;
        float s = (v >= 1.0f) ? 1.0f : 0.0f;
        v *= (1.0f - s);
        float p = s * w;
#pragma unroll
        for (int o = 16; o; o >>= 1) p += __shfl_xor_sync(0xffffffffu, p, o);
        if (lane == 0) red[t * 8 + (tid >> 5)] = p;
    }
    __syncthreads();
    if (tid < TT) {
        float z = b_out[0];
#pragma unroll
        for (int i = 0; i < 8; i++) z += red[tid * 8 + i];
        // inclusive scan across lanes (lane == t)
#pragma unroll
        for (int o = 1; o < 32; o <<= 1) {
            float u = __shfl_up_sync(0xffffffffu, z, o);
            if (lane >= o) z += u;
        }
        out[tid * NB + n] = z;
    }
}

extern "C" void kernel_launch(void* const* d_in, const int* in_sizes, int n_in,
                              void* d_out, int out_size) {
    const float* x      = (const float*)d_in[0];
    const float* W_sdc  = (const float*)d_in[1];
    const float* b_sdc  = (const float*)d_in[2];
    const float* w_syn  = (const float*)d_in[3];
    const float* W_pool = (const float*)d_in[4];
    const float* b_pool = (const float*)d_in[5];
    const float* W_f1   = (const float*)d_in[6];
    const float* b_f1   = (const float*)d_in[7];
    const float* W_f2   = (const float*)d_in[8];
    const float* b_f2   = (const float*)d_in[9];
    const float* W_out  = (const float*)d_in[10];
    const float* b_out  = (const float*)d_in[11];
    float* out = (float*)d_out;

    float* s2   = nullptr;
    float* buf1 = nullptr;
    float* buf2 = nullptr;
    cudaGetSymbolAddress((void**)&s2,   g_s2);
    cudaGetSymbolAddress((void**)&buf1, g_buf1);
    cudaGetSymbolAddress((void**)&buf2, g_buf2);

    // Stage 1: 4096 warps -> 512 blocks x 256 threads
    stage1_kernel<<<(NB * DD) / 8, 256>>>(x, W_sdc, b_sdc, w_syn, W_pool, b_pool);

    // GEMM1: [512,256] @ [256,512] + b_f1 -> buf1.  256 blocks x 128 thr.
    gemm_bias_kernel<AA, 8, 128>
        <<<dim3(F1 / 128, (TT * NB) / 8), 128>>>(s2, W_f1, b_f1, buf1, F1);
    // LIF scan over [T, N*F1]
    lif_scan_kernel<<<(NB * F1) / 256, 256>>>(buf1, NB * F1);

    // GEMM2: [512,512] @ [512,256] + b_f2 -> buf2.  256 blocks x 128 thr.
    gemm_bias_kernel<F1, 4, 128>
        <<<dim3(F2 / 128, (TT * NB) / 4), 128>>>(buf1, W_f2, b_f2, buf2, F2);

    // Fused: LIF scan of pre2 + readout dot + cumulative membrane
    head_kernel<<<NB, 256>>>(W_out, b_out, out);
}

// round 5
// speedup vs baseline: 1.2513x; 1.2513x over previous
#include <cuda_runtime.h>
#include <math.h>

// Problem dims (fixed by reference)
#define TT 32
#define NB 16
#define DD 256
#define AA 256
#define F1 512
#define F2 256
#define MM (TT * NB)   // 512 rows for both GEMMs

// Scratch (allocation-free: __device__ globals)
__device__ float g_s2[MM * DD];            // stage-1 spikes        [512, 256]
__device__ float g_buf1[MM * F1];          // h1 spikes             [512, 512]
__device__ float g_pre2[MM * F2];          // reduced GEMM2 out     [512, 256]
__device__ float g_part[8 * MM * F1];      // split-K partials (max 8 x 1MB)

// ---------------------------------------------------------------------------
// Stage 1: one warp per (n,d) chain. Each thread owns 8 'a' lanes.
// Per t: h = x0*W0[a] + x1*W1[a] + b_sdc[a]
//        i = 0.5*i + h                       (exp_filter, decay 0.5)
//        v1 += (i - v1)*0.5 ; spike; hard reset
//        syn = syn*sd + s1                   (SynapseFilter)
//        z = sum_a syn*W_pool[a] + b_pool    (warp xor-reduce)
//        v2 += (z - v2)*0.5 ; spike; hard reset
// ---------------------------------------------------------------------------
__global__ void stage1_kernel(const float* __restrict__ x,
                              const float* __restrict__ W_sdc,
                              const float* __restrict__ b_sdc,
                              const float* __restrict__ w_syn,
                              const float* __restrict__ W_pool,
                              const float* __restrict__ b_pool) {
    int gwarp = (blockIdx.x * blockDim.x + threadIdx.x) >> 5;
    int lane  = threadIdx.x & 31;
    if (gwarp >= NB * DD) return;
    int n = gwarp >> 8;
    int d = gwarp & (DD - 1);

    float sd = 1.0f - 1.0f / (1.0f + expf(-w_syn[0]));
    float bp = b_pool[0];

    float w0[8], w1[8], bs[8], wp[8];
#pragma unroll
    for (int j = 0; j < 8; j++) {
        int a = j * 32 + lane;
        w0[j] = W_sdc[a];
        w1[j] = W_sdc[AA + a];
        bs[j] = b_sdc[a];
        wp[j] = W_pool[a];
    }

    float is[8], v1[8], sy[8];
#pragma unroll
    for (int j = 0; j < 8; j++) { is[j] = 0.f; v1[j] = 0.f; sy[j] = 0.f; }
    float v2 = 0.f;

    const float* xp = x + (n * 2) * DD + d;
#pragma unroll 1
    for (int t = 0; t < TT; t++) {
        float x0 = xp[(size_t)t * (NB * 2 * DD)];
        float x1 = xp[(size_t)t * (NB * 2 * DD) + DD];
        float z = 0.f;
#pragma unroll
        for (int j = 0; j < 8; j++) {
            float h = x0 * w0[j] + x1 * w1[j] + bs[j];
            is[j] = is[j] * 0.5f + h;
            v1[j] = v1[j] + (is[j] - v1[j]) * 0.5f;
            float s = (v1[j] >= 1.0f) ? 1.0f : 0.0f;
            v1[j] *= (1.0f - s);
            sy[j] = sy[j] * sd + s;
            z += sy[j] * wp[j];
        }
#pragma unroll
        for (int o = 16; o; o >>= 1) z += __shfl_xor_sync(0xffffffffu, z, o);
        z += bp;
        v2 = v2 + (z - v2) * 0.5f;
        float s2 = (v2 >= 1.0f) ? 1.0f : 0.0f;
        v2 *= (1.0f - s2);
        if (lane == 0) g_s2[(t * NB + n) * DD + d] = s2;
    }
}

// ---------------------------------------------------------------------------
// Tiled split-K GEMM: part[z] = A[M, K_z] @ B[K_z, N]  (no bias; reducer adds)
// Tile 32(M) x 64(N), BK=16, 256 threads, thread computes 2x4 outputs.
// grid = (N/64, M/32, SPLIT)  -> 512 blocks for both GEMMs.
// ---------------------------------------------------------------------------
template <int K, int N, int SPLIT>
__global__ void __launch_bounds__(256, 3)
gemm_split_kernel(const float* __restrict__ A,
                  const float* __restrict__ B,
                  float* __restrict__ part) {
    constexpr int KC = K / SPLIT;
    __shared__ float As[16 * 33];   // [k][r], padded
    __shared__ float Bs[16 * 64];   // [k][n]

    int tid  = threadIdx.x;
    int row0 = blockIdx.y * 32;
    int col0 = blockIdx.x * 64;
    int kb0  = blockIdx.z * KC;

    int tx = tid & 15;      // col group of 4
    int ty = tid >> 4;      // row pair

    float acc[2][4];
#pragma unroll
    for (int i = 0; i < 2; i++)
#pragma unroll
        for (int j = 0; j < 4; j++) acc[i][j] = 0.f;

    for (int kb = 0; kb < KC; kb += 16) {
        // A tile: 32 rows x 16 k (coalesced along k)
#pragma unroll
        for (int i = 0; i < 2; i++) {
            int idx = tid + i * 256;
            int r = idx >> 4;
            int k = idx & 15;
            As[k * 33 + r] = A[(size_t)(row0 + r) * K + kb0 + kb + k];
        }
        // B tile: 16 k x 64 n (coalesced along n)
#pragma unroll
        for (int i = 0; i < 4; i++) {
            int idx = tid + i * 256;
            int k = idx >> 6;
            int n = idx & 63;
            Bs[k * 64 + n] = B[(size_t)(kb0 + kb + k) * N + col0 + n];
        }
        __syncthreads();
#pragma unroll
        for (int k = 0; k < 16; k++) {
            float a0 = As[k * 33 + ty * 2];
            float a1 = As[k * 33 + ty * 2 + 1];
            float4 b = *(const float4*)(Bs + k * 64 + tx * 4);
            acc[0][0] = fmaf(a0, b.x, acc[0][0]);
            acc[0][1] = fmaf(a0, b.y, acc[0][1]);
            acc[0][2] = fmaf(a0, b.z, acc[0][2]);
            acc[0][3] = fmaf(a0, b.w, acc[0][3]);
            acc[1][0] = fmaf(a1, b.x, acc[1][0]);
            acc[1][1] = fmaf(a1, b.y, acc[1][1]);
            acc[1][2] = fmaf(a1, b.z, acc[1][2]);
            acc[1][3] = fmaf(a1, b.w, acc[1][3]);
        }
        __syncthreads();
    }

    size_t base = (size_t)blockIdx.z * MM * N;
#pragma unroll
    for (int i = 0; i < 2; i++) {
        float4 o = make_float4(acc[i][0], acc[i][1], acc[i][2], acc[i][3]);
        *(float4*)(part + base + (size_t)(row0 + ty * 2 + i) * N + col0 + tx * 4) = o;
    }
}

// ---------------------------------------------------------------------------
// Reduce 4 split-K partials + bias, then LIF scan over t (register state).
// One thread per (nb, f) chain; chains = NB*F1 = 8192. Coalesced per t.
// ---------------------------------------------------------------------------
__global__ void lif_sum4_kernel(const float* __restrict__ part,
                                const float* __restrict__ bias,
                                float* __restrict__ outbuf) {
    int c = blockIdx.x * blockDim.x + threadIdx.x;
    if (c >= NB * F1) return;
    int nb = c / F1;
    int f  = c - nb * F1;
    float bb = bias[f];
    float v = 0.f;
#pragma unroll 4
    for (int t = 0; t < TT; t++) {
        size_t m = (size_t)(t * NB + nb) * F1 + f;
        float xv = part[m] + part[m + (size_t)MM * F1]
                 + part[m + 2 * (size_t)MM * F1] + part[m + 3 * (size_t)MM * F1] + bb;
        v = v + (xv - v) * 0.5f;
        float s = (v >= 1.0f) ? 1.0f : 0.0f;
        v *= (1.0f - s);
        outbuf[m] = s;
    }
}

// ---------------------------------------------------------------------------
// Reduce 8 split-K partials + bias -> pre2. float4-vectorized.
// ---------------------------------------------------------------------------
__global__ void reduce8_kernel(const float* __restrict__ part,
                               const float* __restrict__ bias,
                               float* __restrict__ outbuf) {
    int e4 = blockIdx.x * blockDim.x + threadIdx.x;      // float4 index
    if (e4 >= (MM * F2) / 4) return;
    int f4 = e4 & (F2 / 4 - 1);
    float4 s = *(const float4*)(bias + f4 * 4);
#pragma unroll
    for (int p = 0; p < 8; p++) {
        float4 v = *(const float4*)(part + (size_t)p * MM * F2 + (size_t)e4 * 4);
        s.x += v.x; s.y += v.y; s.z += v.z; s.w += v.w;
    }
    *(float4*)(outbuf + (size_t)e4 * 4) = s;
}

// ---------------------------------------------------------------------------
// Fused head: LIF-scan pre2 (per-thread register chain, all 32 t preloaded),
// dot with W_out, inclusive cumsum over t. One block (256 thr) per n.
// ---------------------------------------------------------------------------
__global__ void head_kernel(const float* __restrict__ W_out,
                            const float* __restrict__ b_out,
                            float* __restrict__ out) {
    int n    = blockIdx.x;
    int tid  = threadIdx.x;
    int lane = tid & 31;
    __shared__ float red[TT * 8];

    float vals[TT];
#pragma unroll
    for (int t = 0; t < TT; t++)
        vals[t] = g_pre2[(size_t)(t * NB + n) * F2 + tid];

    float w = W_out[tid];
    float v = 0.f;
#pragma unroll
    for (int t = 0; t < TT; t++) {
        v = v + (vals[t] - v) * 0.5f;
        float s = (v >= 1.0f) ? 1.0f : 0.0f;
        v *= (1.0f - s);
        float p = s * w;
#pragma unroll
        for (int o = 16; o; o >>= 1) p += __shfl_xor_sync(0xffffffffu, p, o);
        if (lane == 0) red[t * 8 + (tid >> 5)] = p;
    }
    __syncthreads();
    if (tid < TT) {
        float z = b_out[0];
#pragma unroll
        for (int i = 0; i < 8; i++) z += red[tid * 8 + i];
#pragma unroll
        for (int o = 1; o < 32; o <<= 1) {
            float u = __shfl_up_sync(0xffffffffu, z, o);
            if (lane >= o) z += u;
        }
        out[tid * NB + n] = z;
    }
}

extern "C" void kernel_launch(void* const* d_in, const int* in_sizes, int n_in,
                              void* d_out, int out_size) {
    const float* x      = (const float*)d_in[0];
    const float* W_sdc  = (const float*)d_in[1];
    const float* b_sdc  = (const float*)d_in[2];
    const float* w_syn  = (const float*)d_in[3];
    const float* W_pool = (const float*)d_in[4];
    const float* b_pool = (const float*)d_in[5];
    const float* W_f1   = (const float*)d_in[6];
    const float* b_f1   = (const float*)d_in[7];
    const float* W_f2   = (const float*)d_in[8];
    const float* b_f2   = (const float*)d_in[9];
    const float* W_out  = (const float*)d_in[10];
    const float* b_out  = (const float*)d_in[11];
    float* out = (float*)d_out;

    float *s2 = nullptr, *buf1 = nullptr, *pre2 = nullptr, *part = nullptr;
    cudaGetSymbolAddress((void**)&s2,   g_s2);
    cudaGetSymbolAddress((void**)&buf1, g_buf1);
    cudaGetSymbolAddress((void**)&pre2, g_pre2);
    cudaGetSymbolAddress((void**)&part, g_part);

    // Stage 1: 4096 warps -> 512 blocks x 256 threads
    stage1_kernel<<<(NB * DD) / 8, 256>>>(x, W_sdc, b_sdc, w_syn, W_pool, b_pool);

    // GEMM1: [512,256]@[256,512], split-K=4 -> 512 blocks
    gemm_split_kernel<AA, F1, 4><<<dim3(F1 / 64, MM / 32, 4), 256>>>(s2, W_f1, part);
    // Reduce 4 partials + bias + LIF scan -> buf1
    lif_sum4_kernel<<<(NB * F1) / 128, 128>>>(part, b_f1, buf1);

    // GEMM2: [512,512]@[512,256], split-K=8 -> 512 blocks
    gemm_split_kernel<F1, F2, 8><<<dim3(F2 / 64, MM / 32, 8), 256>>>(buf1, W_f2, part);
    // Reduce 8 partials + bias -> pre2 (float4)
    reduce8_kernel<<<(MM * F2 / 4) / 128, 128>>>(part, b_f2, pre2);

    // Fused: LIF scan of pre2 + readout dot + cumulative membrane
    head_kernel<<<NB, 256>>>(W_out, b_out, out);
}

// round 11
// speedup vs baseline: 1.3757x; 1.0994x over previous
#include <cuda_runtime.h>
#include <math.h>

// Problem dims (fixed by reference)
#define TT 32
#define NB 16
#define DD 256
#define AA 256
#define F1 512
#define F2 256
#define MM (TT * NB)   // 512 rows for both GEMMs

// Scratch (allocation-free: __device__ globals)
__device__ float g_s2[MM * DD];            // stage-1 spikes        [512, 256]
__device__ float g_buf1[MM * F1];          // h1 spikes             [512, 512]
__device__ float g_part[8 * MM * F1];      // split-K partials (max 8 x 1MB)

// ---------------------------------------------------------------------------
// Stage 1: one warp per (n,d) chain. Each thread owns 8 'a' lanes.
// ---------------------------------------------------------------------------
__global__ void stage1_kernel(const float* __restrict__ x,
                              const float* __restrict__ W_sdc,
                              const float* __restrict__ b_sdc,
                              const float* __restrict__ w_syn,
                              const float* __restrict__ W_pool,
                              const float* __restrict__ b_pool) {
    int gwarp = (blockIdx.x * blockDim.x + threadIdx.x) >> 5;
    int lane  = threadIdx.x & 31;
    if (gwarp >= NB * DD) return;
    int n = gwarp >> 8;
    int d = gwarp & (DD - 1);

    float sd = 1.0f - 1.0f / (1.0f + expf(-w_syn[0]));
    float bp = b_pool[0];

    float w0[8], w1[8], bs[8], wp[8];
#pragma unroll
    for (int j = 0; j < 8; j++) {
        int a = j * 32 + lane;
        w0[j] = W_sdc[a];
        w1[j] = W_sdc[AA + a];
        bs[j] = b_sdc[a];
        wp[j] = W_pool[a];
    }

    float is[8], v1[8], sy[8];
#pragma unroll
    for (int j = 0; j < 8; j++) { is[j] = 0.f; v1[j] = 0.f; sy[j] = 0.f; }
    float v2 = 0.f;

    const float* xp = x + (n * 2) * DD + d;
#pragma unroll 2
    for (int t = 0; t < TT; t++) {
        float x0 = xp[(size_t)t * (NB * 2 * DD)];
        float x1 = xp[(size_t)t * (NB * 2 * DD) + DD];
        float z = 0.f;
#pragma unroll
        for (int j = 0; j < 8; j++) {
            float h = x0 * w0[j] + x1 * w1[j] + bs[j];
            is[j] = is[j] * 0.5f + h;
            v1[j] = v1[j] + (is[j] - v1[j]) * 0.5f;
            bool fire = (v1[j] >= 1.0f);
            float s = fire ? 1.0f : 0.0f;
            v1[j] = fire ? 0.0f : v1[j];          // exact hard reset (select)
            sy[j] = sy[j] * sd + s;
            z += sy[j] * wp[j];
        }
#pragma unroll
        for (int o = 16; o; o >>= 1) z += __shfl_xor_sync(0xffffffffu, z, o);
        z += bp;
        v2 = v2 + (z - v2) * 0.5f;
        bool f2s = (v2 >= 1.0f);
        float s2 = f2s ? 1.0f : 0.0f;
        v2 = f2s ? 0.0f : v2;
        if (lane == 0) g_s2[(t * NB + n) * DD + d] = s2;
    }
}

// ---------------------------------------------------------------------------
// Tiled split-K GEMM v3: part[z] = A[M,K_z] @ B[K_z,N]
// Tile 64(M) x 64(N), BK=16, 256 threads, 4x4 outputs/thread.
// Global loads for tile i+1 are prefetched into registers before the compute
// phase of tile i (software pipeline) so L2 latency overlaps FMAs.
// grid = (N/64, M/64, SPLIT)  -> 256 blocks for both GEMMs, 2 blocks/SM.
// ---------------------------------------------------------------------------
template <int K, int N, int SPLIT>
__global__ void __launch_bounds__(256, 2)
gemm64_kernel(const float* __restrict__ A,
              const float* __restrict__ B,
              float* __restrict__ part) {
    constexpr int KC = K / SPLIT;
    __shared__ float As[16 * 72];   // [k][m], stride 72 (16B-aligned, conflict-free)
    __shared__ float Bs[16 * 64];   // [k][n]

    int tid  = threadIdx.x;
    int row0 = blockIdx.y * 64;
    int col0 = blockIdx.x * 64;
    int kb0  = blockIdx.z * KC;

    int tx = tid & 15;              // n group of 4
    int ty = tid >> 4;              // m group of 4

    int ar = tid >> 2;              // A load: row 0..63
    int ak = (tid & 3) * 4;         //         k  0,4,8,12
    int bk = tid >> 4;              // B load: k 0..15
    int bn = (tid & 15) * 4;        //         n group

    const float* Aptr = A + (size_t)(row0 + ar) * K + kb0 + ak;
    const float* Bptr = B + (size_t)(kb0 + bk) * N + col0 + bn;

    float acc[4][4];
#pragma unroll
    for (int i = 0; i < 4; i++)
#pragma unroll
        for (int j = 0; j < 4; j++) acc[i][j] = 0.f;

    // Prologue: load first tile
    float4 av = *(const float4*)(Aptr);
    float4 bv = *(const float4*)(Bptr + 0);

#pragma unroll
    for (int kb = 0; kb < KC; kb += 16) {
        As[(ak + 0) * 72 + ar] = av.x;   // transpose A into [k][m]
        As[(ak + 1) * 72 + ar] = av.y;
        As[(ak + 2) * 72 + ar] = av.z;
        As[(ak + 3) * 72 + ar] = av.w;
        *(float4*)(Bs + bk * 64 + bn) = bv;
        __syncthreads();

        // Prefetch next tile while computing this one
        if (kb + 16 < KC) {
            av = *(const float4*)(Aptr + kb + 16);
            bv = *(const float4*)(Bptr + (size_t)(kb + 16) * N);
        }

#pragma unroll
        for (int k = 0; k < 16; k++) {
            float4 a = *(const float4*)(As + k * 72 + ty * 4);
            float4 b = *(const float4*)(Bs + k * 64 + tx * 4);
            acc[0][0] = fmaf(a.x, b.x, acc[0][0]);
            acc[0][1] = fmaf(a.x, b.y, acc[0][1]);
            acc[0][2] = fmaf(a.x, b.z, acc[0][2]);
            acc[0][3] = fmaf(a.x, b.w, acc[0][3]);
            acc[1][0] = fmaf(a.y, b.x, acc[1][0]);
            acc[1][1] = fmaf(a.y, b.y, acc[1][1]);
            acc[1][2] = fmaf(a.y, b.z, acc[1][2]);
            acc[1][3] = fmaf(a.y, b.w, acc[1][3]);
            acc[2][0] = fmaf(a.z, b.x, acc[2][0]);
            acc[2][1] = fmaf(a.z, b.y, acc[2][1]);
            acc[2][2] = fmaf(a.z, b.z, acc[2][2]);
            acc[2][3] = fmaf(a.z, b.w, acc[2][3]);
            acc[3][0] = fmaf(a.w, b.x, acc[3][0]);
            acc[3][1] = fmaf(a.w, b.y, acc[3][1]);
            acc[3][2] = fmaf(a.w, b.z, acc[3][2]);
            acc[3][3] = fmaf(a.w, b.w, acc[3][3]);
        }
        __syncthreads();
    }

    size_t base = (size_t)blockIdx.z * MM * N;
#pragma unroll
    for (int i = 0; i < 4; i++) {
        float4 o = make_float4(acc[i][0], acc[i][1], acc[i][2], acc[i][3]);
        *(float4*)(part + base + (size_t)(row0 + ty * 4 + i) * N + col0 + tx * 4) = o;
    }
}

// ---------------------------------------------------------------------------
// Reduce 4 split-K partials + bias, then LIF scan over t (register state).
// One thread per (nb, f) chain; chains = NB*F1 = 8192. The 4 partial loads
// per t are issued as independent LDGs (MLP=4) before the dependent sum.
// ---------------------------------------------------------------------------
__global__ void lif_sum4_kernel(const float* __restrict__ part,
                                const float* __restrict__ bias,
                                float* __restrict__ outbuf) {
    int c = blockIdx.x * blockDim.x + threadIdx.x;
    if (c >= NB * F1) return;
    int nb = c / F1;
    int f  = c - nb * F1;
    float bb = bias[f];
    float v = 0.f;
#pragma unroll 4
    for (int t = 0; t < TT; t++) {
        size_t m = (size_t)(t * NB + nb) * F1 + f;
        float p0 = part[m];
        float p1 = part[m + (size_t)MM * F1];
        float p2 = part[m + 2 * (size_t)MM * F1];
        float p3 = part[m + 3 * (size_t)MM * F1];
        float xv = (p0 + p1) + (p2 + p3) + bb;
        v = v + (xv - v) * 0.5f;
        bool fire = (v >= 1.0f);
        float s = fire ? 1.0f : 0.0f;
        v = fire ? 0.0f : v;
        outbuf[m] = s;
    }
}

// ---------------------------------------------------------------------------
// Fused head: sum 8 split-K partials + bias (same order as the old reduce8),
// LIF-scan per-thread register chain, dot with W_out, inclusive cumsum over t.
// One block (256 thr = F2 lanes) per n. xv[32] precomputed for load overlap.
// ---------------------------------------------------------------------------
__global__ void head_kernel(const float* __restrict__ part,
                            const float* __restrict__ bias2,
                            const float* __restrict__ W_out,
                            const float* __restrict__ b_out,
                            float* __restrict__ out) {
    int n    = blockIdx.x;
    int tid  = threadIdx.x;
    int lane = tid & 31;
    __shared__ float red[TT * 8];

    float bb = bias2[tid];
    float xv[TT];
#pragma unroll
    for (int t = 0; t < TT; t++) {
        size_t m = (size_t)(t * NB + n) * F2 + tid;
        float s = bb;
#pragma unroll
        for (int p = 0; p < 8; p++)
            s += part[(size_t)p * MM * F2 + m];
        xv[t] = s;
    }

    float w = W_out[tid];
    float v = 0.f;
#pragma unroll
    for (int t = 0; t < TT; t++) {
        v = v + (xv[t] - v) * 0.5f;
        bool fire = (v >= 1.0f);
        float s = fire ? 1.0f : 0.0f;
        v = fire ? 0.0f : v;
        float p = s * w;
#pragma unroll
        for (int o = 16; o; o >>= 1) p += __shfl_xor_sync(0xffffffffu, p, o);
        if (lane == 0) red[t * 8 + (tid >> 5)] = p;
    }
    __syncthreads();
    if (tid < TT) {
        float z = b_out[0];
#pragma unroll
        for (int i = 0; i < 8; i++) z += red[tid * 8 + i];
#pragma unroll
        for (int o = 1; o < 32; o <<= 1) {
            float u = __shfl_up_sync(0xffffffffu, z, o);
            if (lane >= o) z += u;
        }
        out[tid * NB + n] = z;
    }
}

extern "C" void kernel_launch(void* const* d_in, const int* in_sizes, int n_in,
                              void* d_out, int out_size) {
    const float* x      = (const float*)d_in[0];
    const float* W_sdc  = (const float*)d_in[1];
    const float* b_sdc  = (const float*)d_in[2];
    const float* w_syn  = (const float*)d_in[3];
    const float* W_pool = (const float*)d_in[4];
    const float* b_pool = (const float*)d_in[5];
    const float* W_f1   = (const float*)d_in[6];
    const float* b_f1   = (const float*)d_in[7];
    const float* W_f2   = (const float*)d_in[8];
    const float* b_f2   = (const float*)d_in[9];
    const float* W_out  = (const float*)d_in[10];
    const float* b_out  = (const float*)d_in[11];
    float* out = (float*)d_out;

    float *s2 = nullptr, *buf1 = nullptr, *part = nullptr;
    cudaGetSymbolAddress((void**)&s2,   g_s2);
    cudaGetSymbolAddress((void**)&buf1, g_buf1);
    cudaGetSymbolAddress((void**)&part, g_part);

    // Stage 1: 4096 warps -> 512 blocks x 256 threads
    stage1_kernel<<<(NB * DD) / 8, 256>>>(x, W_sdc, b_sdc, w_syn, W_pool, b_pool);

    // GEMM1: [512,256]@[256,512], split-K=4 -> grid (8,8,4) = 256 blocks
    gemm64_kernel<AA, F1, 4><<<dim3(F1 / 64, MM / 64, 4), 256>>>(s2, W_f1, part);
    // Reduce 4 partials + bias + LIF scan -> buf1
    lif_sum4_kernel<<<(NB * F1) / 128, 128>>>(part, b_f1, buf1);

    // GEMM2: [512,512]@[512,256], split-K=8 -> grid (4,8,8) = 256 blocks
    gemm64_kernel<F1, F2, 8><<<dim3(F2 / 64, MM / 64, 8), 256>>>(buf1, W_f2, part);

    // Fused: 8-way partial reduce + bias + LIF scan + readout + cumsum
    head_kernel<<<NB, 256>>>(part, b_f2, W_out, b_out, out);
}